// round 5
// baseline (speedup 1.0000x reference)
#include <cuda_runtime.h>
#include <math.h>
#include <stdint.h>

// Problem dims
#define SQ   2048
#define DM   1024
#define NH   16
#define DK   64
#define BB   2
#define ROWS (BB*SQ)   // 4096
#define BHN  (BB*NH)   // 32

// ---------------- scratch (static device memory; no allocs allowed) ----------------
__device__ float g_Q  [ (size_t)ROWS*DM ];
__device__ float g_K  [ (size_t)ROWS*DM ];
__device__ float g_V  [ (size_t)ROWS*DM ];
__device__ float g_ctx[ (size_t)ROWS*DM ];
__device__ float g_fc [ (size_t)ROWS*DM ];
__device__ float g_attn[ (size_t)BHN*SQ*SQ ];   // 512 MB scores/attn scratch
__device__ int   g_maskmode;

// ---------------- mask dtype detection ----------------
// jax bool mask may arrive as int32 / float32 / uint8 / bf16. Detect from byte patterns.
__global__ void detect_mask_kernel(const void* __restrict__ mask)
{
    __shared__ int ok[3];   // [0]=int32 ok, [1]=f32 ok, [2]=bf16 ok
    int tid = threadIdx.x;
    if (tid < 3) ok[tid] = 1;
    __syncthreads();
    const unsigned int*   pi = (const unsigned int*)mask;
    const unsigned short* ps = (const unsigned short*)mask;
    bool i32ok = true, f32ok = true, bfok = true;
    for (int i = tid; i < 4096; i += 256) {
        unsigned int v = pi[i];
        if (v > 1u) i32ok = false;
        if (v != 0u && v != 0x3F800000u) f32ok = false;
    }
    for (int i = tid; i < 4096; i += 256) {
        unsigned short v = ps[i];
        if (v != 0 && v != 0x3F80) bfok = false;
    }
    if (!i32ok) atomicAnd(&ok[0], 0);
    if (!f32ok) atomicAnd(&ok[1], 0);
    if (!bfok)  atomicAnd(&ok[2], 0);
    __syncthreads();
    if (tid == 0)
        g_maskmode = ok[0] ? 0 : (ok[1] ? 1 : (ok[2] ? 3 : 2));
}

__device__ __forceinline__ bool mask_at(const void* __restrict__ mask, size_t idx, int mode)
{
    if (mode == 0) return ((const int*)mask)[idx] != 0;
    if (mode == 1) return ((const float*)mask)[idx] != 0.0f;
    if (mode == 2) return ((const unsigned char*)mask)[idx] != 0;
    return ((const unsigned short*)mask)[idx] != 0;
}

// ---------------- generic C = alpha * A[M,K] * B[N,K]^T  (both row-major over K) ----
// BM=BN=128, BK=16, 256 threads, 8x8 per thread. M,N multiples of 128; K multiple of 16.
__global__ void __launch_bounds__(256, 2) sgemm_abt(
    const float* __restrict__ A, int lda,
    const float* __restrict__ B, int ldb,
    float* __restrict__ C, int ldc,
    int K, float alpha)
{
    __shared__ float As[16][132];
    __shared__ float Bs[16][132];
    const int tid = threadIdx.x;
    const int bm = blockIdx.y * 128;
    const int bn = blockIdx.x * 128;
    const int tx = tid & 15;          // 16 col-groups
    const int ty = tid >> 4;          // 16 row-groups
    const int lr = tid >> 2;          // 0..63
    const int lc = (tid & 3) << 2;    // 0,4,8,12

    float acc[8][8];
    #pragma unroll
    for (int i = 0; i < 8; i++)
        #pragma unroll
        for (int j = 0; j < 8; j++) acc[i][j] = 0.f;

    for (int k0 = 0; k0 < K; k0 += 16) {
        #pragma unroll
        for (int it = 0; it < 2; it++) {
            int r = lr + it * 64;
            float4 va = *(const float4*)(A + (size_t)(bm + r) * lda + k0 + lc);
            As[lc + 0][r] = va.x; As[lc + 1][r] = va.y;
            As[lc + 2][r] = va.z; As[lc + 3][r] = va.w;
            float4 vb = *(const float4*)(B + (size_t)(bn + r) * ldb + k0 + lc);
            Bs[lc + 0][r] = vb.x; Bs[lc + 1][r] = vb.y;
            Bs[lc + 2][r] = vb.z; Bs[lc + 3][r] = vb.w;
        }
        __syncthreads();
        #pragma unroll
        for (int kk = 0; kk < 16; kk++) {
            float4 a0 = *(const float4*)&As[kk][ty * 8];
            float4 a1 = *(const float4*)&As[kk][ty * 8 + 4];
            float4 b0 = *(const float4*)&Bs[kk][tx * 8];
            float4 b1 = *(const float4*)&Bs[kk][tx * 8 + 4];
            float ra[8] = {a0.x,a0.y,a0.z,a0.w,a1.x,a1.y,a1.z,a1.w};
            float rb[8] = {b0.x,b0.y,b0.z,b0.w,b1.x,b1.y,b1.z,b1.w};
            #pragma unroll
            for (int i = 0; i < 8; i++)
                #pragma unroll
                for (int j = 0; j < 8; j++) acc[i][j] += ra[i] * rb[j];
        }
        __syncthreads();
    }
    #pragma unroll
    for (int i = 0; i < 8; i++) {
        int r = bm + ty * 8 + i;
        #pragma unroll
        for (int j = 0; j < 8; j += 4) {
            float4 v;
            v.x = acc[i][j+0] * alpha; v.y = acc[i][j+1] * alpha;
            v.z = acc[i][j+2] * alpha; v.w = acc[i][j+3] * alpha;
            *(float4*)(C + (size_t)r * ldc + bn + tx * 8 + j) = v;
        }
    }
}

// ---------------- scores = mask ? -1e9 : (Q_bh K_bh^T) / 8, per (b,h) ---------------
__global__ void __launch_bounds__(256, 2) qk_scores(const void* __restrict__ mask)
{
    const int bh = blockIdx.z;
    const int b = bh >> 4, h = bh & 15;
    const float* A = g_Q + (size_t)b * SQ * DM + h * DK;   // lda = DM
    const float* Bp = g_K + (size_t)b * SQ * DM + h * DK;  // ldb = DM
    float* C = g_attn + (size_t)bh * SQ * SQ;              // ldc = SQ

    __shared__ float As[16][132];
    __shared__ float Bs[16][132];
    const int tid = threadIdx.x;
    const int bm = blockIdx.y * 128;
    const int bn = blockIdx.x * 128;
    const int tx = tid & 15;
    const int ty = tid >> 4;
    const int lr = tid >> 2;
    const int lc = (tid & 3) << 2;

    float acc[8][8];
    #pragma unroll
    for (int i = 0; i < 8; i++)
        #pragma unroll
        for (int j = 0; j < 8; j++) acc[i][j] = 0.f;

    for (int k0 = 0; k0 < DK; k0 += 16) {
        #pragma unroll
        for (int it = 0; it < 2; it++) {
            int r = lr + it * 64;
            float4 va = *(const float4*)(A + (size_t)(bm + r) * DM + k0 + lc);
            As[lc + 0][r] = va.x; As[lc + 1][r] = va.y;
            As[lc + 2][r] = va.z; As[lc + 3][r] = va.w;
            float4 vb = *(const float4*)(Bp + (size_t)(bn + r) * DM + k0 + lc);
            Bs[lc + 0][r] = vb.x; Bs[lc + 1][r] = vb.y;
            Bs[lc + 2][r] = vb.z; Bs[lc + 3][r] = vb.w;
        }
        __syncthreads();
        #pragma unroll
        for (int kk = 0; kk < 16; kk++) {
            float4 a0 = *(const float4*)&As[kk][ty * 8];
            float4 a1 = *(const float4*)&As[kk][ty * 8 + 4];
            float4 b0 = *(const float4*)&Bs[kk][tx * 8];
            float4 b1 = *(const float4*)&Bs[kk][tx * 8 + 4];
            float ra[8] = {a0.x,a0.y,a0.z,a0.w,a1.x,a1.y,a1.z,a1.w};
            float rb[8] = {b0.x,b0.y,b0.z,b0.w,b1.x,b1.y,b1.z,b1.w};
            #pragma unroll
            for (int i = 0; i < 8; i++)
                #pragma unroll
                for (int j = 0; j < 8; j++) acc[i][j] += ra[i] * rb[j];
        }
        __syncthreads();
    }
    const int mode = g_maskmode;
    #pragma unroll
    for (int i = 0; i < 8; i++) {
        int q = bm + ty * 8 + i;
        #pragma unroll
        for (int j = 0; j < 8; j += 4) {
            float4 v;
            #pragma unroll
            for (int jj = 0; jj < 4; jj++) {
                int kc = bn + tx * 8 + j + jj;
                size_t midx = ((size_t)b * SQ + q) * SQ + kc;
                float s = acc[i][j + jj] * 0.125f;
                ((float*)&v)[jj] = mask_at(mask, midx, mode) ? -1e9f : s;
            }
            *(float4*)(C + (size_t)q * SQ + bn + tx * 8 + j) = v;
        }
    }
}

// ---------------- row softmax over 2048, one block per row --------------------------
__global__ void __launch_bounds__(256) softmax_rows(float* __restrict__ dst)
{
    const size_t row = blockIdx.x;
    const float* x = g_attn + row * SQ;
    float* y = (dst ? dst : g_attn) + row * SQ;
    const int tid = threadIdx.x, lane = tid & 31, warp = tid >> 5;
    __shared__ float sm[8];
    float v[8];
    float m = -3.0e38f;
    #pragma unroll
    for (int i = 0; i < 8; i++) { v[i] = x[i * 256 + tid]; m = fmaxf(m, v[i]); }
    #pragma unroll
    for (int o = 16; o; o >>= 1) m = fmaxf(m, __shfl_xor_sync(0xffffffffu, m, o));
    if (lane == 0) sm[warp] = m;
    __syncthreads();
    m = sm[lane & 7];
    #pragma unroll
    for (int o = 4; o; o >>= 1) m = fmaxf(m, __shfl_xor_sync(0xffffffffu, m, o));
    float s = 0.f;
    #pragma unroll
    for (int i = 0; i < 8; i++) { v[i] = expf(v[i] - m); s += v[i]; }
    #pragma unroll
    for (int o = 16; o; o >>= 1) s += __shfl_xor_sync(0xffffffffu, s, o);
    __syncthreads();
    if (lane == 0) sm[warp] = s;
    __syncthreads();
    s = sm[lane & 7];
    #pragma unroll
    for (int o = 4; o; o >>= 1) s += __shfl_xor_sync(0xffffffffu, s, o);
    const float inv = 1.0f / s;
    #pragma unroll
    for (int i = 0; i < 8; i++) y[i * 256 + tid] = v[i] * inv;
}

// ---------------- context = attn @ V per (b,h): [2048,2048]x[2048,64] ---------------
__global__ void __launch_bounds__(256, 2) pv_gemm(const float* __restrict__ attn_src)
{
    const int bh = blockIdx.z;
    const int b = bh >> 4, h = bh & 15;
    const float* A = (attn_src ? attn_src : g_attn) + (size_t)bh * SQ * SQ; // lda=SQ
    const float* Bp = g_V + (size_t)b * SQ * DM + h * DK;                    // ldb=DM (K x N rows)
    float* C = g_ctx + (size_t)b * SQ * DM + h * DK;                         // ldc=DM

    __shared__ float As[16][132];
    __shared__ float Bs[16][68];
    const int tid = threadIdx.x;
    const int bm = blockIdx.y * 128;
    const int tx = tid & 15;          // cols tx*4
    const int ty = tid >> 4;          // rows ty*8
    const int lr = tid >> 2;
    const int lc = (tid & 3) << 2;
    const int brow = tid >> 4;        // 0..15
    const int bcol = (tid & 15) << 2; // 0..60

    float acc[8][4];
    #pragma unroll
    for (int i = 0; i < 8; i++)
        #pragma unroll
        for (int j = 0; j < 4; j++) acc[i][j] = 0.f;

    for (int k0 = 0; k0 < SQ; k0 += 16) {
        #pragma unroll
        for (int it = 0; it < 2; it++) {
            int r = lr + it * 64;
            float4 va = *(const float4*)(A + (size_t)(bm + r) * SQ + k0 + lc);
            As[lc + 0][r] = va.x; As[lc + 1][r] = va.y;
            As[lc + 2][r] = va.z; As[lc + 3][r] = va.w;
        }
        {
            float4 vb = *(const float4*)(Bp + (size_t)(k0 + brow) * DM + bcol);
            *(float4*)&Bs[brow][bcol] = vb;
        }
        __syncthreads();
        #pragma unroll
        for (int kk = 0; kk < 16; kk++) {
            float4 a0 = *(const float4*)&As[kk][ty * 8];
            float4 a1 = *(const float4*)&As[kk][ty * 8 + 4];
            float4 b0 = *(const float4*)&Bs[kk][tx * 4];
            float ra[8] = {a0.x,a0.y,a0.z,a0.w,a1.x,a1.y,a1.z,a1.w};
            float rb[4] = {b0.x,b0.y,b0.z,b0.w};
            #pragma unroll
            for (int i = 0; i < 8; i++)
                #pragma unroll
                for (int j = 0; j < 4; j++) acc[i][j] += ra[i] * rb[j];
        }
        __syncthreads();
    }
    #pragma unroll
    for (int i = 0; i < 8; i++) {
        int r = bm + ty * 8 + i;
        float4 v; v.x = acc[i][0]; v.y = acc[i][1]; v.z = acc[i][2]; v.w = acc[i][3];
        *(float4*)(C + (size_t)r * DM + tx * 4) = v;
    }
}

// ---------------- out = LayerNorm(fc + residual), one block per row of 1024 ---------
__global__ void __launch_bounds__(256) add_ln(const float* __restrict__ res, float* __restrict__ dst)
{
    const size_t row = blockIdx.x;
    const float* f = g_fc + row * DM;
    const float* r = res + row * DM;
    float* o = (dst ? dst : g_Q) + row * DM;
    const int tid = threadIdx.x, lane = tid & 31, warp = tid >> 5;
    __shared__ float sm[8];
    float x[4];
    float s = 0.f;
    #pragma unroll
    for (int i = 0; i < 4; i++) { x[i] = f[i * 256 + tid] + r[i * 256 + tid]; s += x[i]; }
    #pragma unroll
    for (int off = 16; off; off >>= 1) s += __shfl_xor_sync(0xffffffffu, s, off);
    if (lane == 0) sm[warp] = s;
    __syncthreads();
    s = sm[lane & 7];
    #pragma unroll
    for (int off = 4; off; off >>= 1) s += __shfl_xor_sync(0xffffffffu, s, off);
    const float mean = s * (1.0f / DM);
    float s2 = 0.f;
    #pragma unroll
    for (int i = 0; i < 4; i++) { float d = x[i] - mean; s2 += d * d; }
    #pragma unroll
    for (int off = 16; off; off >>= 1) s2 += __shfl_xor_sync(0xffffffffu, s2, off);
    __syncthreads();
    if (lane == 0) sm[warp] = s2;
    __syncthreads();
    s2 = sm[lane & 7];
    #pragma unroll
    for (int off = 4; off; off >>= 1) s2 += __shfl_xor_sync(0xffffffffu, s2, off);
    const float inv = rsqrtf(s2 * (1.0f / DM) + 1e-5f);
    #pragma unroll
    for (int i = 0; i < 4; i++) o[i * 256 + tid] = (x[i] - mean) * inv;
}

// ---------------- launch -----------------------------------------------------------
extern "C" void kernel_launch(void* const* d_in, const int* in_sizes, int n_in,
                              void* d_out, int out_size)
{
    const float* iQ  = (const float*)d_in[0];
    const float* iK  = (const float*)d_in[1];
    const float* iV  = (const float*)d_in[2];
    const void*  msk = d_in[3];
    const float* WQ  = (const float*)d_in[4];
    const float* WK  = (const float*)d_in[5];
    const float* WV  = (const float*)d_in[6];
    const float* Wfc = (const float*)d_in[7];
    float* out = (float*)d_out;

    const long long LN_N  = (long long)ROWS * DM;        // 4,194,304
    const long long ATT_N = (long long)BHN * SQ * SQ;    // 134,217,728
    float* attn_out = nullptr;   // null -> scratch only
    float* ln_out   = out;
    if ((long long)out_size >= LN_N + ATT_N) {
        attn_out = out + LN_N;
    } else if ((long long)out_size == ATT_N) {
        attn_out = out;
        ln_out = nullptr;        // discard LN into scratch
    }

    void* p;
    cudaGetSymbolAddress(&p, g_Q);   float* pQ   = (float*)p;
    cudaGetSymbolAddress(&p, g_K);   float* pK   = (float*)p;
    cudaGetSymbolAddress(&p, g_V);   float* pV   = (float*)p;
    cudaGetSymbolAddress(&p, g_ctx); float* pCtx = (float*)p;
    cudaGetSymbolAddress(&p, g_fc);  float* pFc  = (float*)p;

    detect_mask_kernel<<<1, 256>>>(msk);

    dim3 gp(DM / 128, ROWS / 128);     // (8, 32)
    sgemm_abt<<<gp, 256>>>(iQ, DM, WQ, DM, pQ, DM, DM, 1.0f);
    sgemm_abt<<<gp, 256>>>(iK, DM, WK, DM, pK, DM, DM, 1.0f);
    sgemm_abt<<<gp, 256>>>(iV, DM, WV, DM, pV, DM, DM, 1.0f);

    dim3 gs(SQ / 128, SQ / 128, BHN);  // (16, 16, 32)
    qk_scores<<<gs, 256>>>(msk);

    softmax_rows<<<(unsigned)(BHN * SQ), 256>>>(attn_out);

    dim3 gv(1, SQ / 128, BHN);         // (1, 16, 32)
    pv_gemm<<<gv, 256>>>(attn_out);

    sgemm_abt<<<gp, 256>>>(pCtx, DM, Wfc, DM, pFc, DM, DM, 1.0f);

    add_ln<<<(unsigned)ROWS, 256>>>(iQ, ln_out);
}

// round 7
// speedup vs baseline: 1.8581x; 1.8581x over previous
#include <cuda_runtime.h>
#include <cuda_bf16.h>
#include <math.h>
#include <stdint.h>

// Problem dims
#define SQ   2048
#define DM   1024
#define NH   16
#define DK   64
#define BB   2
#define ROWS (BB*SQ)   // 4096
#define BHN  (BB*NH)   // 32

// ---------------- scratch (static device memory; no allocs allowed) ----------------
__device__ float g_Q  [ (size_t)ROWS*DM ];
__device__ float g_K  [ (size_t)ROWS*DM ];
__device__ float g_V  [ (size_t)ROWS*DM ];
__device__ float g_ctx[ (size_t)ROWS*DM ];
__device__ float g_fc [ (size_t)ROWS*DM ];
__device__ float g_attn[ (size_t)BHN*SQ*SQ ];   // 512 MB scores scratch
__device__ int   g_maskmode;

// ---------------- mask dtype detection ----------------
__global__ void detect_mask_kernel(const void* __restrict__ mask)
{
    __shared__ int ok[3];
    int tid = threadIdx.x;
    if (tid < 3) ok[tid] = 1;
    __syncthreads();
    const unsigned int*   pi = (const unsigned int*)mask;
    const unsigned short* ps = (const unsigned short*)mask;
    bool i32ok = true, f32ok = true, bfok = true;
    for (int i = tid; i < 4096; i += 256) {
        unsigned int v = pi[i];
        if (v > 1u) i32ok = false;
        if (v != 0u && v != 0x3F800000u) f32ok = false;
    }
    for (int i = tid; i < 4096; i += 256) {
        unsigned short v = ps[i];
        if (v != 0 && v != 0x3F80) bfok = false;
    }
    if (!i32ok) atomicAnd(&ok[0], 0);
    if (!f32ok) atomicAnd(&ok[1], 0);
    if (!bfok)  atomicAnd(&ok[2], 0);
    __syncthreads();
    if (tid == 0)
        g_maskmode = ok[0] ? 0 : (ok[1] ? 1 : (ok[2] ? 3 : 2));
}

__device__ __forceinline__ bool mask_at(const void* __restrict__ mask, size_t idx, int mode)
{
    if (mode == 0) return ((const int*)mask)[idx] != 0;
    if (mode == 1) return ((const float*)mask)[idx] != 0.0f;
    if (mode == 2) return ((const unsigned char*)mask)[idx] != 0;
    return ((const unsigned short*)mask)[idx] != 0;
}

// ======================= helpers =======================
__device__ __forceinline__ uint32_t smem_u32(const void* p) {
    uint32_t a;
    asm("{ .reg .u64 t; cvta.to.shared.u64 t, %1; cvt.u32.u64 %0, t; }" : "=r"(a) : "l"(p));
    return a;
}
// SW64 swizzle for 64-byte rows: XOR bits[5:4] with bits[8:7]
__device__ __forceinline__ uint32_t swz64(uint32_t b) { return b ^ ((b >> 3) & 0x30); }

// split f32 -> bf16 hi + bf16 lo
__device__ __forceinline__ void split4(float4 v, uint2& uh, uint2& ul)
{
    __nv_bfloat16 hx = __float2bfloat16(v.x), hy = __float2bfloat16(v.y);
    __nv_bfloat16 hz = __float2bfloat16(v.z), hw = __float2bfloat16(v.w);
    __nv_bfloat16 lx = __float2bfloat16(v.x - __bfloat162float(hx));
    __nv_bfloat16 ly = __float2bfloat16(v.y - __bfloat162float(hy));
    __nv_bfloat16 lz = __float2bfloat16(v.z - __bfloat162float(hz));
    __nv_bfloat16 lw = __float2bfloat16(v.w - __bfloat162float(hw));
    union { __nv_bfloat162 b2[2]; uint2 u; } th, tl;
    th.b2[0] = __halves2bfloat162(hx, hy); th.b2[1] = __halves2bfloat162(hz, hw);
    tl.b2[0] = __halves2bfloat162(lx, ly); tl.b2[1] = __halves2bfloat162(lz, lw);
    uh = th.u; ul = tl.u;
}

#define LDMX4(r, addr) \
    asm volatile("ldmatrix.sync.aligned.m8n8.x4.shared.b16 {%0,%1,%2,%3}, [%4];" \
        : "=r"((r)[0]), "=r"((r)[1]), "=r"((r)[2]), "=r"((r)[3]) : "r"(addr))

#define MMA_BF16(cc, a, b0_, b1_) \
    asm volatile("mma.sync.aligned.m16n8k16.row.col.f32.bf16.bf16.f32 " \
        "{%0,%1,%2,%3}, {%4,%5,%6,%7}, {%8,%9}, {%0,%1,%2,%3};" \
        : "+f"((cc)[0]), "+f"((cc)[1]), "+f"((cc)[2]), "+f"((cc)[3]) \
        : "r"((a)[0]), "r"((a)[1]), "r"((a)[2]), "r"((a)[3]), "r"(b0_), "r"(b1_))

// ======================= bf16x3 mma.sync GEMM =======================
// MODE 0: dense  C[4096,1024] = A[4096,1024] * B[1024,1024]^T  (both K-major, ld=DM)
// MODE 1: qk     per bh: scores = mask ? -1e9 : (Q K^T)/8 -> g_attn
// MODE 2: pv     per bh: ctx = attn[2048,2048] @ V[2048,64]  (V transposed on load)
template<int MODE>
__global__ void __launch_bounds__(256, 2) mma_gemm(const float* __restrict__ Ap,
                                                   const float* __restrict__ Bp,
                                                   float* __restrict__ Cp,
                                                   const void* __restrict__ mask)
{
    constexpr int BN    = (MODE == 2) ? 64 : 128;
    constexpr int NSTEP = (MODE == 0) ? 32 : ((MODE == 1) ? 2 : 64);
    constexpr int BNW   = BN / 2;          // per-warp n extent
    constexpr int NF    = BNW / 8;         // n8 fragments per warp
    constexpr int SM_AH = 0;
    constexpr int SM_AL = 8192;
    constexpr int SM_BH = 16384;
    constexpr int SM_BL = SM_BH + BN * 64;

    __shared__ __align__(16) char smem[SM_BH + 2 * BN * 64];

    const int tid = threadIdx.x, lane = tid & 31, wid = tid >> 5;
    const int bm = blockIdx.y * 128;
    const int bn = blockIdx.x * BN;

    int b = 0;
    const float* A; const float* Bsrc; float* C;
    int lda, ldc;
    if (MODE == 0) {
        A = Ap + (size_t)bm * DM; lda = DM;
        Bsrc = Bp + (size_t)bn * DM;
        C = Cp; ldc = DM;
    } else if (MODE == 1) {
        int bh = blockIdx.z; b = bh >> 4; int h = bh & 15;
        A = g_Q + ((size_t)b * SQ + bm) * DM + h * DK; lda = DM;
        Bsrc = g_K + ((size_t)b * SQ + bn) * DM + h * DK;
        C = g_attn + (size_t)bh * SQ * SQ; ldc = SQ;
    } else {
        int bh = blockIdx.z; b = bh >> 4; int h = bh & 15;
        A = Ap + (size_t)bh * SQ * SQ + (size_t)bm * SQ; lda = SQ;   // attn
        Bsrc = g_V + (size_t)b * SQ * DM + h * DK;                    // V (k-major rows)
        C = g_ctx + (size_t)b * SQ * DM + h * DK; ldc = DM;
    }

    const uint32_t sb  = smem_u32(smem);
    const uint32_t sAh = sb + SM_AH, sAl = sb + SM_AL;
    const uint32_t sBh = sb + SM_BH, sBl = sb + SM_BL;

    const int wm = (wid & 3) * 32;         // warp m offset within tile
    const int wn = (wid >> 2) * BNW;       // warp n offset within tile
    // ldmatrix lane address components
    const int ar = lane & 15;              // A: row 0..15
    const int ac = (lane >> 4) << 3;       // A: k col 0/8
    const int br = (lane & 7) + ((lane & 16) >> 1);  // B: n row 0..15
    const int bc = lane & 8;               // B: k col 0/8

    float c[2][NF][4];
    #pragma unroll
    for (int mi = 0; mi < 2; mi++)
        #pragma unroll
        for (int nf = 0; nf < NF; nf++)
            #pragma unroll
            for (int j = 0; j < 4; j++) c[mi][nf][j] = 0.f;

    for (int it = 0; it < NSTEP; ++it) {
        const int k0g = it * 32;
        __syncthreads();   // previous chunk's compute done before overwrite

        // ---- A tile: 128 rows x 32 f32 -> hi/lo bf16, SW64 swizzled ----
        {
            const float* src = A + k0g;
            float4 v[4];
            #pragma unroll
            for (int i = 0; i < 4; i++) {
                int idx = tid + (i << 8);
                v[i] = *(const float4*)(src + (size_t)(idx >> 3) * lda + ((idx & 7) << 2));
            }
            #pragma unroll
            for (int i = 0; i < 4; i++) {
                int idx = tid + (i << 8);
                int r = idx >> 3, c4 = (idx & 7) << 2;
                uint2 uh, ul; split4(v[i], uh, ul);
                uint32_t sw = swz64((uint32_t)(r * 64 + (c4 << 1)));
                *(uint2*)(smem + SM_AH + sw) = uh;
                *(uint2*)(smem + SM_AL + sw) = ul;
            }
        }
        // ---- B tile ----
        if (MODE != 2) {
            const float* src = Bsrc + k0g;
            float4 v[4];
            #pragma unroll
            for (int i = 0; i < 4; i++) {
                int idx = tid + (i << 8);
                v[i] = *(const float4*)(src + (size_t)(idx >> 3) * DM + ((idx & 7) << 2));
            }
            #pragma unroll
            for (int i = 0; i < 4; i++) {
                int idx = tid + (i << 8);
                int r = idx >> 3, c4 = (idx & 7) << 2;
                uint2 uh, ul; split4(v[i], uh, ul);
                uint32_t sw = swz64((uint32_t)(r * 64 + (c4 << 1)));
                *(uint2*)(smem + SM_BH + sw) = uh;
                *(uint2*)(smem + SM_BL + sw) = ul;
            }
        } else {
            // transpose-load V: B[n][k] = V[k0g+kr][n], 64 n-rows x 32 k-cols
            const float* src = Bsrc + (size_t)k0g * DM;
            #pragma unroll
            for (int i = 0; i < 2; i++) {
                int idx = tid + (i << 8);
                int kr = idx >> 4, n4 = (idx & 15) << 2;
                float4 v = *(const float4*)(src + (size_t)kr * DM + n4);
                float f[4] = {v.x, v.y, v.z, v.w};
                #pragma unroll
                for (int j = 0; j < 4; j++) {
                    __nv_bfloat16 hi = __float2bfloat16(f[j]);
                    __nv_bfloat16 lo = __float2bfloat16(f[j] - __bfloat162float(hi));
                    uint32_t sw = swz64((uint32_t)((n4 + j) * 64 + kr * 2));
                    *(__nv_bfloat16*)(smem + SM_BH + sw) = hi;
                    *(__nv_bfloat16*)(smem + SM_BL + sw) = lo;
                }
            }
        }
        __syncthreads();

        // ---- compute: 2 k16 steps over the 32-col chunk ----
        #pragma unroll
        for (int ks = 0; ks < 2; ++ks) {
            uint32_t ah[2][4], al[2][4];
            #pragma unroll
            for (int mi = 0; mi < 2; mi++) {
                uint32_t off = swz64((uint32_t)((wm + mi * 16 + ar) * 64 + (ks * 16 + ac) * 2));
                LDMX4(ah[mi], sAh + off);
                LDMX4(al[mi], sAl + off);
            }
            #pragma unroll
            for (int p = 0; p < NF / 2; p++) {
                uint32_t bh[4], bl[4];
                uint32_t off = swz64((uint32_t)((wn + p * 16 + br) * 64 + (ks * 16 + bc) * 2));
                LDMX4(bh, sBh + off);
                LDMX4(bl, sBl + off);
                #pragma unroll
                for (int hh = 0; hh < 2; hh++) {
                    const int nf = p * 2 + hh;
                    #pragma unroll
                    for (int mi = 0; mi < 2; mi++) {
                        MMA_BF16(c[mi][nf], ah[mi], bh[hh * 2], bh[hh * 2 + 1]);
                        MMA_BF16(c[mi][nf], ah[mi], bl[hh * 2], bl[hh * 2 + 1]);
                        MMA_BF16(c[mi][nf], al[mi], bh[hh * 2], bh[hh * 2 + 1]);
                    }
                }
            }
        }
    }

    // ---- epilogue ----
    const int mm = (MODE == 1) ? g_maskmode : 0;
    #pragma unroll
    for (int mi = 0; mi < 2; mi++) {
        #pragma unroll
        for (int nf = 0; nf < NF; nf++) {
            int row = bm + wm + mi * 16 + (lane >> 2);
            int col = bn + wn + nf * 8 + ((lane & 3) << 1);
            float2 v0 = make_float2(c[mi][nf][0], c[mi][nf][1]);
            float2 v1 = make_float2(c[mi][nf][2], c[mi][nf][3]);
            if (MODE == 1) {
                size_t m0 = ((size_t)b * SQ + row) * SQ + col;
                size_t m1 = m0 + (size_t)8 * SQ;
                v0.x = mask_at(mask, m0,     mm) ? -1e9f : v0.x * 0.125f;
                v0.y = mask_at(mask, m0 + 1, mm) ? -1e9f : v0.y * 0.125f;
                v1.x = mask_at(mask, m1,     mm) ? -1e9f : v1.x * 0.125f;
                v1.y = mask_at(mask, m1 + 1, mm) ? -1e9f : v1.y * 0.125f;
            }
            *(float2*)(C + (size_t)row * ldc + col)       = v0;
            *(float2*)(C + (size_t)(row + 8) * ldc + col) = v1;
        }
    }
}

// ---------------- row softmax over 2048, one block per row --------------------------
__global__ void __launch_bounds__(256) softmax_rows(float* __restrict__ dst)
{
    const size_t row = blockIdx.x;
    const float* x = g_attn + row * SQ;
    float* y = (dst ? dst : g_attn) + row * SQ;
    const int tid = threadIdx.x, lane = tid & 31, warp = tid >> 5;
    __shared__ float sm[8];
    float v[8];
    float m = -3.0e38f;
    #pragma unroll
    for (int i = 0; i < 8; i++) { v[i] = x[i * 256 + tid]; m = fmaxf(m, v[i]); }
    #pragma unroll
    for (int o = 16; o; o >>= 1) m = fmaxf(m, __shfl_xor_sync(0xffffffffu, m, o));
    if (lane == 0) sm[warp] = m;
    __syncthreads();
    m = sm[lane & 7];
    #pragma unroll
    for (int o = 4; o; o >>= 1) m = fmaxf(m, __shfl_xor_sync(0xffffffffu, m, o));
    float s = 0.f;
    #pragma unroll
    for (int i = 0; i < 8; i++) { v[i] = expf(v[i] - m); s += v[i]; }
    #pragma unroll
    for (int o = 16; o; o >>= 1) s += __shfl_xor_sync(0xffffffffu, s, o);
    __syncthreads();
    if (lane == 0) sm[warp] = s;
    __syncthreads();
    s = sm[lane & 7];
    #pragma unroll
    for (int o = 4; o; o >>= 1) s += __shfl_xor_sync(0xffffffffu, s, o);
    const float inv = 1.0f / s;
    #pragma unroll
    for (int i = 0; i < 8; i++) y[i * 256 + tid] = v[i] * inv;
}

// ---------------- out = LayerNorm(fc + residual), one block per row of 1024 ---------
__global__ void __launch_bounds__(256) add_ln(const float* __restrict__ res, float* __restrict__ dst)
{
    const size_t row = blockIdx.x;
    const float* f = g_fc + row * DM;
    const float* r = res + row * DM;
    float* o = (dst ? dst : g_Q) + row * DM;
    const int tid = threadIdx.x, lane = tid & 31, warp = tid >> 5;
    __shared__ float sm[8];
    float x[4];
    float s = 0.f;
    #pragma unroll
    for (int i = 0; i < 4; i++) { x[i] = f[i * 256 + tid] + r[i * 256 + tid]; s += x[i]; }
    #pragma unroll
    for (int off = 16; off; off >>= 1) s += __shfl_xor_sync(0xffffffffu, s, off);
    if (lane == 0) sm[warp] = s;
    __syncthreads();
    s = sm[lane & 7];
    #pragma unroll
    for (int off = 4; off; off >>= 1) s += __shfl_xor_sync(0xffffffffu, s, off);
    const float mean = s * (1.0f / DM);
    float s2 = 0.f;
    #pragma unroll
    for (int i = 0; i < 4; i++) { float d = x[i] - mean; s2 += d * d; }
    #pragma unroll
    for (int off = 16; off; off >>= 1) s2 += __shfl_xor_sync(0xffffffffu, s2, off);
    __syncthreads();
    if (lane == 0) sm[warp] = s2;
    __syncthreads();
    s2 = sm[lane & 7];
    #pragma unroll
    for (int off = 4; off; off >>= 1) s2 += __shfl_xor_sync(0xffffffffu, s2, off);
    const float inv = rsqrtf(s2 * (1.0f / DM) + 1e-5f);
    #pragma unroll
    for (int i = 0; i < 4; i++) o[i * 256 + tid] = (x[i] - mean) * inv;
}

// ---------------- launch -----------------------------------------------------------
extern "C" void kernel_launch(void* const* d_in, const int* in_sizes, int n_in,
                              void* d_out, int out_size)
{
    const float* iQ  = (const float*)d_in[0];
    const float* iK  = (const float*)d_in[1];
    const float* iV  = (const float*)d_in[2];
    const void*  msk = d_in[3];
    const float* WQ  = (const float*)d_in[4];
    const float* WK  = (const float*)d_in[5];
    const float* WV  = (const float*)d_in[6];
    const float* Wfc = (const float*)d_in[7];
    float* out = (float*)d_out;

    const long long LN_N  = (long long)ROWS * DM;        // 4,194,304
    const long long ATT_N = (long long)BHN * SQ * SQ;    // 134,217,728
    float* attn_out = nullptr;
    float* ln_out   = out;
    if ((long long)out_size >= LN_N + ATT_N) {
        attn_out = out + LN_N;
    } else if ((long long)out_size == ATT_N) {
        attn_out = out;
        ln_out = nullptr;
    }

    void* p;
    cudaGetSymbolAddress(&p, g_Q);    float* pQ    = (float*)p;
    cudaGetSymbolAddress(&p, g_K);    float* pK    = (float*)p;
    cudaGetSymbolAddress(&p, g_V);    float* pV    = (float*)p;
    cudaGetSymbolAddress(&p, g_ctx);  float* pCtx  = (float*)p;
    cudaGetSymbolAddress(&p, g_fc);   float* pFc   = (float*)p;
    cudaGetSymbolAddress(&p, g_attn); float* pAttn = (float*)p;

    detect_mask_kernel<<<1, 256>>>(msk);

    dim3 gp(DM / 128, ROWS / 128);               // (8, 32)
    mma_gemm<0><<<gp, 256>>>(iQ, WQ, pQ, nullptr);
    mma_gemm<0><<<gp, 256>>>(iK, WK, pK, nullptr);
    mma_gemm<0><<<gp, 256>>>(iV, WV, pV, nullptr);

    dim3 gs(SQ / 128, SQ / 128, BHN);            // (16, 16, 32)
    mma_gemm<1><<<gs, 256>>>(nullptr, nullptr, nullptr, msk);

    softmax_rows<<<(unsigned)(BHN * SQ), 256>>>(attn_out);

    const float* attn_src = attn_out ? attn_out : pAttn;
    dim3 gv(1, SQ / 128, BHN);                   // (1, 16, 32)
    mma_gemm<2><<<gv, 256>>>(attn_src, nullptr, nullptr, nullptr);

    mma_gemm<0><<<gp, 256>>>(pCtx, Wfc, pFc, nullptr);

    add_ln<<<(unsigned)ROWS, 256>>>(iQ, ln_out);
}